// round 5
// baseline (speedup 1.0000x reference)
#include <cuda_runtime.h>
#include <cuda_bf16.h>

#define DIMV   512
#define NROWS  16384
#define KCODES 8192

#define BM 128
#define BN 128
#define BK 128                     // int8 K-chunk = 128 bytes/row
#define NCHUNK (DIMV / BK)         // 4
#define NSTAGE 3
#define STAGE_BYTES 32768          // A 16KB + B 16KB
#define NSEG  (KCODES / 32)
#define CPR   (NSEG * 2)
#define EPSF  6.0f

#define QSCALE (127.0f / 6.0f)
#define INV2S2 (2.0f * 36.0f / (127.0f * 127.0f))

// ---------------- device globals ------------------------------------------
__device__ __align__(16) unsigned g_x8[(size_t)NROWS * DIMV / 4];
__device__ __align__(16) unsigned g_e8[(size_t)KCODES * DIMV / 4];
__device__ float g_esq[KCODES];
__device__ unsigned long long g_cand[(size_t)NROWS * CPR];

// ---------------- packing -------------------------------------------------
__device__ __forceinline__ unsigned long long pack_score(float s, int idx) {
    unsigned u = __float_as_uint(s);
    u = (u & 0x80000000u) ? ~u : (u | 0x80000000u);
    return ((unsigned long long)u << 32) | (unsigned)(KCODES - 1 - idx);
}
__device__ __forceinline__ float unpack_score(unsigned long long p) {
    unsigned u = (unsigned)(p >> 32);
    u = (u & 0x80000000u) ? (u ^ 0x80000000u) : ~u;
    return __uint_as_float(u);
}
__device__ __forceinline__ int unpack_idx(unsigned long long p) {
    return KCODES - 1 - (int)(unsigned)(p & 0xFFFFFFFFu);
}
__device__ __forceinline__ void merge2(unsigned long long& a, unsigned long long& b,
                                       unsigned long long p) {
    if (p > a) { b = a; a = p; } else if (p > b) { b = p; }
}
__device__ __forceinline__ unsigned smem_u32(const void* p) {
    unsigned a;
    asm("{ .reg .u64 t; cvta.to.shared.u64 t, %1; cvt.u32.u64 %0, t; }"
        : "=r"(a) : "l"(p));
    return a;
}
__device__ __forceinline__ int q8(float v) {
    v = fminf(fmaxf(v, -6.0f), 6.0f);
    return __float2int_rn(v * QSCALE);
}

// ---------------- kernel 1: int8 quantize + |e|^2 --------------------------
__global__ void vq_prep(const float* __restrict__ x, const float* __restrict__ embed) {
    int b = blockIdx.x, tid = threadIdx.x;   // NROWS blocks x 128 threads
    float4 v = ((const float4*)(x + (size_t)b * DIMV))[tid];
    unsigned pk = (unsigned)(q8(v.x) & 255) | ((unsigned)(q8(v.y) & 255) << 8) |
                  ((unsigned)(q8(v.z) & 255) << 16) | ((unsigned)(q8(v.w) & 255) << 24);
    g_x8[(size_t)b * (DIMV / 4) + tid] = pk;

    if (b < KCODES) {
        float4 e = ((const float4*)(embed + (size_t)b * DIMV))[tid];
        unsigned qk = (unsigned)(q8(e.x) & 255) | ((unsigned)(q8(e.y) & 255) << 8) |
                      ((unsigned)(q8(e.z) & 255) << 16) | ((unsigned)(q8(e.w) & 255) << 24);
        g_e8[(size_t)b * (DIMV / 4) + tid] = qk;

        float s = e.x * e.x + e.y * e.y + e.z * e.z + e.w * e.w;
        #pragma unroll
        for (int o = 16; o > 0; o >>= 1) s += __shfl_down_sync(0xffffffffu, s, o);
        __shared__ float red[4];
        if ((tid & 31) == 0) red[tid >> 5] = s;
        __syncthreads();
        if (tid == 0) g_esq[b] = red[0] + red[1] + red[2] + red[3];
    }
}

// ---------------- kernel 2: int8 IMMA GEMM + top-2 epilogue ----------------
// CTA 128x128, BK=128 (bytes), 256 threads, warp grid 2x4, warp tile 64x32.
__global__ __launch_bounds__(256, 2)
void vq_gemm() {
    extern __shared__ char smem[];            // 3 stages x (A 16KB + B 16KB)
    __shared__ float s_esq[BN];

    const int tid = threadIdx.x, lane = tid & 31, wid = tid >> 5;
    const int wm = wid >> 2, wn = wid & 3;
    const int rowBase = blockIdx.y * BM;
    const int colBase = blockIdx.x * BN;
    const unsigned sb = smem_u32(smem);

    if (tid < BN) s_esq[tid] = g_esq[colBase + tid];

    int acc[4][4][4];
    #pragma unroll
    for (int mt = 0; mt < 4; mt++)
        #pragma unroll
        for (int nt = 0; nt < 4; nt++)
            #pragma unroll
            for (int q = 0; q < 4; q++) acc[mt][nt][q] = 0;

    const char* xb = (const char*)g_x8;
    const char* eb = (const char*)g_e8;

    // stage loader: A 128x128B, B 128x128B, XOR-swizzled 16B chunks
    #define ISSUE_STAGE(c) do {                                              \
        const unsigned _aB = sb + ((c) % NSTAGE) * STAGE_BYTES;              \
        const unsigned _bB = _aB + 16384u;                                   \
        const char* _xp = xb + (size_t)rowBase * DIMV + (c) * BK;            \
        const char* _ep = eb + (size_t)colBase * DIMV + (c) * BK;            \
        _Pragma("unroll")                                                    \
        for (int _it = 0; _it < 4; _it++) {                                  \
            int _u = tid + _it * 256;                                        \
            int _r = _u >> 3, _c = _u & 7;                                   \
            unsigned _off = _r * 128 + (((_c ^ (_r & 7))) << 4);             \
            asm volatile("cp.async.cg.shared.global [%0], [%1], 16;"         \
                :: "r"(_aB + _off), "l"(_xp + (size_t)_r * DIMV + _c * 16)); \
            asm volatile("cp.async.cg.shared.global [%0], [%1], 16;"         \
                :: "r"(_bB + _off), "l"(_ep + (size_t)_r * DIMV + _c * 16)); \
        }                                                                    \
        asm volatile("cp.async.commit_group;");                              \
    } while (0)

    ISSUE_STAGE(0);
    ISSUE_STAGE(1);

    #pragma unroll 1
    for (int c = 0; c < NCHUNK; c++) {
        if (c < NCHUNK - 1) asm volatile("cp.async.wait_group 1;");
        else                asm volatile("cp.async.wait_group 0;");
        __syncthreads();
        if (c + 2 < NCHUNK) ISSUE_STAGE(c + 2);

        const unsigned aBase = sb + (c % NSTAGE) * STAGE_BYTES;
        const unsigned bBase = aBase + 16384u;

        #pragma unroll
        for (int ks = 0; ks < 4; ks++) {      // 4 x k32 per 128B chunk
            unsigned af[4][4], bf[2][4];
            #pragma unroll
            for (int mt = 0; mt < 4; mt++) {
                // tiles: t0 rows0-7/kLo, t1 rows8-15/kLo, t2 rows0-7/kHi, t3 rows8-15/kHi
                int rA = wm * 64 + mt * 16 + ((lane >> 3) & 1) * 8 + (lane & 7);
                int cA = ks * 2 + (lane >> 4);
                unsigned addr = aBase + rA * 128 + (((cA ^ (rA & 7))) << 4);
                asm volatile("ldmatrix.sync.aligned.m8n8.x4.shared.b16 "
                             "{%0,%1,%2,%3}, [%4];"
                             : "=r"(af[mt][0]), "=r"(af[mt][1]),
                               "=r"(af[mt][2]), "=r"(af[mt][3]) : "r"(addr));
            }
            #pragma unroll
            for (int pr = 0; pr < 2; pr++) {
                // tiles: t0 n0-7/kLo, t1 n0-7/kHi, t2 n8-15/kLo, t3 n8-15/kHi
                int rB = wn * 32 + pr * 16 + ((lane >> 4) & 1) * 8 + (lane & 7);
                int cB = ks * 2 + ((lane >> 3) & 1);
                unsigned addr = bBase + rB * 128 + (((cB ^ (rB & 7))) << 4);
                asm volatile("ldmatrix.sync.aligned.m8n8.x4.shared.b16 "
                             "{%0,%1,%2,%3}, [%4];"
                             : "=r"(bf[pr][0]), "=r"(bf[pr][1]),
                               "=r"(bf[pr][2]), "=r"(bf[pr][3]) : "r"(addr));
            }
            #pragma unroll
            for (int mt = 0; mt < 4; mt++)
                #pragma unroll
                for (int pr = 0; pr < 2; pr++) {
                    asm volatile(
                        "mma.sync.aligned.m16n8k32.row.col.s32.s8.s8.s32 "
                        "{%0,%1,%2,%3}, {%4,%5,%6,%7}, {%8,%9}, {%0,%1,%2,%3};"
                        : "+r"(acc[mt][2*pr][0]), "+r"(acc[mt][2*pr][1]),
                          "+r"(acc[mt][2*pr][2]), "+r"(acc[mt][2*pr][3])
                        : "r"(af[mt][0]), "r"(af[mt][1]),
                          "r"(af[mt][2]), "r"(af[mt][3]),
                          "r"(bf[pr][0]), "r"(bf[pr][1]));
                    asm volatile(
                        "mma.sync.aligned.m16n8k32.row.col.s32.s8.s8.s32 "
                        "{%0,%1,%2,%3}, {%4,%5,%6,%7}, {%8,%9}, {%0,%1,%2,%3};"
                        : "+r"(acc[mt][2*pr+1][0]), "+r"(acc[mt][2*pr+1][1]),
                          "+r"(acc[mt][2*pr+1][2]), "+r"(acc[mt][2*pr+1][3])
                        : "r"(af[mt][0]), "r"(af[mt][1]),
                          "r"(af[mt][2]), "r"(af[mt][3]),
                          "r"(bf[pr][2]), "r"(bf[pr][3]));
                }
        }
        __syncthreads();
    }

    // ---- epilogue: per-(row, 32-col segment) top-2 -------------------------
    const int gq = lane >> 2;
    const int qt = lane & 3;
    float esqv[4][2];
    #pragma unroll
    for (int nt = 0; nt < 4; nt++) {
        int cl = wn * 32 + nt * 8 + qt * 2;
        esqv[nt][0] = s_esq[cl];
        esqv[nt][1] = s_esq[cl + 1];
    }
    const int seg = (colBase + wn * 32) >> 5;

    #pragma unroll
    for (int mt = 0; mt < 4; mt++) {
        int r0 = rowBase + wm * 64 + mt * 16 + gq;
        int r1 = r0 + 8;
        unsigned long long a0 = 0, b0 = 0, a1 = 0, b1 = 0;
        #pragma unroll
        for (int nt = 0; nt < 4; nt++) {
            int cg = colBase + wn * 32 + nt * 8 + qt * 2;
            merge2(a0, b0, pack_score((float)acc[mt][nt][0] * INV2S2 - esqv[nt][0], cg));
            merge2(a0, b0, pack_score((float)acc[mt][nt][1] * INV2S2 - esqv[nt][1], cg + 1));
            merge2(a1, b1, pack_score((float)acc[mt][nt][2] * INV2S2 - esqv[nt][0], cg));
            merge2(a1, b1, pack_score((float)acc[mt][nt][3] * INV2S2 - esqv[nt][1], cg + 1));
        }
        #pragma unroll
        for (int off = 1; off <= 2; off <<= 1) {
            unsigned long long xa0 = __shfl_xor_sync(0xffffffffu, a0, off);
            unsigned long long xb0 = __shfl_xor_sync(0xffffffffu, b0, off);
            unsigned long long xa1 = __shfl_xor_sync(0xffffffffu, a1, off);
            unsigned long long xb1 = __shfl_xor_sync(0xffffffffu, b1, off);
            merge2(a0, b0, xa0); merge2(a0, b0, xb0);
            merge2(a1, b1, xa1); merge2(a1, b1, xb1);
        }
        if (qt == 0) {
            g_cand[(size_t)r0 * CPR + seg * 2]     = a0;
            g_cand[(size_t)r0 * CPR + seg * 2 + 1] = b0;
            g_cand[(size_t)r1 * CPR + seg * 2]     = a1;
            g_cand[(size_t)r1 * CPR + seg * 2 + 1] = b1;
        }
    }
}

// ---------------- kernel 3: exact fp32 rescore + gather --------------------
__global__ void vq_rescore(const float* __restrict__ x, const float* __restrict__ embed,
                           float* __restrict__ out, int write_idx) {
    const int row = blockIdx.x, tid = threadIdx.x;   // 128 threads
    const int wid = tid >> 5, lid = tid & 31;
    __shared__ unsigned long long s_max4[4];
    __shared__ int s_cnt;
    __shared__ int s_idx[64];
    __shared__ float s_red[4];
    __shared__ unsigned long long s_win;
    if (tid == 0) s_cnt = 0;

    const unsigned long long* cd = g_cand + (size_t)row * CPR;
    unsigned long long m = 0;
    #pragma unroll
    for (int i = tid; i < CPR; i += 128) m = max(m, cd[i]);
    #pragma unroll
    for (int o = 16; o > 0; o >>= 1)
        m = max(m, __shfl_down_sync(0xffffffffu, m, o));
    if (lid == 0) s_max4[wid] = m;
    __syncthreads();
    m = max(max(s_max4[0], s_max4[1]), max(s_max4[2], s_max4[3]));
    const float thr = unpack_score(m) - EPSF;

    for (int i = tid; i < CPR; i += 128) {
        unsigned long long p = cd[i];
        if (unpack_score(p) >= thr) {
            int k = atomicAdd(&s_cnt, 1);
            if (k < 64) s_idx[k] = unpack_idx(p);
        }
    }
    __syncthreads();
    const int cnt = min(s_cnt, 64);

    const float4 xv = ((const float4*)(x + (size_t)row * DIMV))[tid];
    unsigned long long best = 0ULL;
    for (int c = 0; c < cnt; c++) {
        const int idx = s_idx[c];
        float4 ev = ((const float4*)(embed + (size_t)idx * DIMV))[tid];
        float d = xv.x * ev.x + xv.y * ev.y + xv.z * ev.z + xv.w * ev.w;
        #pragma unroll
        for (int o = 16; o > 0; o >>= 1) d += __shfl_down_sync(0xffffffffu, d, o);
        if (lid == 0) s_red[wid] = d;
        __syncthreads();
        if (tid == 0) {
            float dot = s_red[0] + s_red[1] + s_red[2] + s_red[3];
            unsigned long long p = pack_score(2.0f * dot - g_esq[idx], idx);
            if (p > best) best = p;
        }
        __syncthreads();
    }
    if (tid == 0) s_win = best;
    __syncthreads();

    const int widx = unpack_idx(s_win);
    float4 ev = ((const float4*)(embed + (size_t)widx * DIMV))[tid];
    ((float4*)(out + (size_t)row * DIMV))[tid] = ev;
    if (write_idx && tid == 0)
        out[(size_t)NROWS * DIMV + row] = (float)widx;
}

// ---------------- launch ----------------------------------------------------
extern "C" void kernel_launch(void* const* d_in, const int* in_sizes, int n_in,
                              void* d_out, int out_size) {
    const float* x     = (const float*)d_in[0];
    const float* embed = (const float*)d_in[1];
    float* out = (float*)d_out;

    cudaFuncSetAttribute(vq_gemm, cudaFuncAttributeMaxDynamicSharedMemorySize,
                         NSTAGE * STAGE_BYTES);

    vq_prep<<<NROWS, 128>>>(x, embed);

    dim3 grid(KCODES / BN, NROWS / BM);   // 64 x 128
    vq_gemm<<<grid, 256, NSTAGE * STAGE_BYTES>>>();

    int write_idx = (out_size >= NROWS * DIMV + NROWS) ? 1 : 0;
    vq_rescore<<<NROWS, 128>>>(x, embed, out, write_idx);
}

// round 6
// speedup vs baseline: 1.9820x; 1.9820x over previous
#include <cuda_runtime.h>
#include <cuda_bf16.h>

#define DIMV   512
#define NROWS  16384
#define KCODES 8192

#define BM 128
#define BN 256
#define BK 64
#define NCHUNK (DIMV / BK)        // 8
#define NSTAGE 3
#define STAGE_BYTES 49152         // A 16KB + B 32KB
#define NTHR 512
#define NSEG  (KCODES / 32)       // 256 segments of 32 codes
#define CPR   (NSEG * 2)          // 512 candidate slots per row
#define EPSF  1.0f

// ---------------- device globals (no runtime allocation allowed) ----------
__device__ __align__(16) __nv_bfloat16 g_xb[(size_t)NROWS * DIMV];
__device__ __align__(16) __nv_bfloat16 g_eb[(size_t)KCODES * DIMV];
__device__ float g_esq[KCODES];
__device__ unsigned long long g_cand[(size_t)NROWS * CPR];

// ---------------- packing: monotonic (score, smaller-idx-wins) ------------
__device__ __forceinline__ unsigned long long pack_score(float s, int idx) {
    unsigned u = __float_as_uint(s);
    u = (u & 0x80000000u) ? ~u : (u | 0x80000000u);
    return ((unsigned long long)u << 32) | (unsigned)(KCODES - 1 - idx);
}
__device__ __forceinline__ float unpack_score(unsigned long long p) {
    unsigned u = (unsigned)(p >> 32);
    u = (u & 0x80000000u) ? (u ^ 0x80000000u) : ~u;
    return __uint_as_float(u);
}
__device__ __forceinline__ int unpack_idx(unsigned long long p) {
    return KCODES - 1 - (int)(unsigned)(p & 0xFFFFFFFFu);
}
__device__ __forceinline__ void merge2(unsigned long long& a, unsigned long long& b,
                                       unsigned long long p) {
    if (p > a) { b = a; a = p; } else if (p > b) { b = p; }
}
__device__ __forceinline__ unsigned smem_u32(const void* p) {
    unsigned a;
    asm("{ .reg .u64 t; cvta.to.shared.u64 t, %1; cvt.u32.u64 %0, t; }"
        : "=r"(a) : "l"(p));
    return a;
}

// ---------------- kernel 1: bf16 conversion + |e|^2 ------------------------
__global__ void vq_prep(const float* __restrict__ x, const float* __restrict__ embed) {
    int b = blockIdx.x, tid = threadIdx.x;   // NROWS blocks x 128 threads
    float4 v = ((const float4*)(x + (size_t)b * DIMV))[tid];
    __nv_bfloat162 p0, p1;
    p0.x = __float2bfloat16(v.x); p0.y = __float2bfloat16(v.y);
    p1.x = __float2bfloat16(v.z); p1.y = __float2bfloat16(v.w);
    uint2 pk = make_uint2(*(unsigned*)&p0, *(unsigned*)&p1);
    *(uint2*)(g_xb + (size_t)b * DIMV + tid * 4) = pk;

    if (b < KCODES) {
        float4 e = ((const float4*)(embed + (size_t)b * DIMV))[tid];
        __nv_bfloat162 q0, q1;
        q0.x = __float2bfloat16(e.x); q0.y = __float2bfloat16(e.y);
        q1.x = __float2bfloat16(e.z); q1.y = __float2bfloat16(e.w);
        uint2 qk = make_uint2(*(unsigned*)&q0, *(unsigned*)&q1);
        *(uint2*)(g_eb + (size_t)b * DIMV + tid * 4) = qk;

        float s = e.x * e.x + e.y * e.y + e.z * e.z + e.w * e.w;
        #pragma unroll
        for (int o = 16; o > 0; o >>= 1) s += __shfl_down_sync(0xffffffffu, s, o);
        __shared__ float red[4];
        if ((tid & 31) == 0) red[tid >> 5] = s;
        __syncthreads();
        if (tid == 0) g_esq[b] = red[0] + red[1] + red[2] + red[3];
    }
}

// ---------------- kernel 2: bf16 HMMA GEMM, CTA 128x256, 512 thr -----------
// Warp grid 2(m) x 8(n), warp tile 64x32 (same per-warp shape as round 3).
__global__ __launch_bounds__(NTHR, 1)
void vq_gemm() {
    extern __shared__ char smem[];                // 3 stages x (A 16KB + B 32KB)
    __shared__ float s_esq[BN];

    const int tid = threadIdx.x, lane = tid & 31, wid = tid >> 5;
    const int wm = wid >> 3, wn = wid & 7;        // 2 x 8 warp grid
    const int rowBase = blockIdx.y * BM;
    const int colBase = blockIdx.x * BN;
    const unsigned sb = smem_u32(smem);

    if (tid < BN) s_esq[tid] = g_esq[colBase + tid];

    float acc[4][4][4];
    #pragma unroll
    for (int mt = 0; mt < 4; mt++)
        #pragma unroll
        for (int nt = 0; nt < 4; nt++)
            #pragma unroll
            for (int q = 0; q < 4; q++) acc[mt][nt][q] = 0.f;

    // stage loader: A 128x64 (2 iters), B 256x64 (4 iters), XOR-swizzled
    #define ISSUE_STAGE(c) do {                                              \
        const unsigned _aB = sb + ((c) % NSTAGE) * STAGE_BYTES;              \
        const unsigned _bB = _aB + 16384u;                                   \
        const __nv_bfloat16* _xp = g_xb + (size_t)rowBase * DIMV + (c) * BK; \
        const __nv_bfloat16* _ep = g_eb + (size_t)colBase * DIMV + (c) * BK; \
        _Pragma("unroll")                                                    \
        for (int _it = 0; _it < 2; _it++) {                                  \
            int _u = tid + _it * NTHR;                                       \
            int _r = _u >> 3, _c = _u & 7;                                   \
            unsigned _off = _r * 128 + (((_c ^ (_r & 7))) << 4);             \
            asm volatile("cp.async.cg.shared.global [%0], [%1], 16;"         \
                :: "r"(_aB + _off), "l"(_xp + (size_t)_r * DIMV + _c * 8));  \
        }                                                                    \
        _Pragma("unroll")                                                    \
        for (int _it = 0; _it < 4; _it++) {                                  \
            int _u = tid + _it * NTHR;                                       \
            int _r = _u >> 3, _c = _u & 7;                                   \
            unsigned _off = _r * 128 + (((_c ^ (_r & 7))) << 4);             \
            asm volatile("cp.async.cg.shared.global [%0], [%1], 16;"         \
                :: "r"(_bB + _off), "l"(_ep + (size_t)_r * DIMV + _c * 8));  \
        }                                                                    \
        asm volatile("cp.async.commit_group;");                              \
    } while (0)

    ISSUE_STAGE(0);
    ISSUE_STAGE(1);

    #pragma unroll 1
    for (int c = 0; c < NCHUNK; c++) {
        if (c < NCHUNK - 1) asm volatile("cp.async.wait_group 1;");
        else                asm volatile("cp.async.wait_group 0;");
        __syncthreads();
        // after the barrier, buffer (c+2)%3 == (c-1)%3 is dead: safe to refill
        if (c + 2 < NCHUNK) ISSUE_STAGE(c + 2);

        const unsigned aBase = sb + (c % NSTAGE) * STAGE_BYTES;
        const unsigned bBase = aBase + 16384u;

        #pragma unroll
        for (int ks = 0; ks < 4; ks++) {
            unsigned af[4][4], bf[2][4];
            #pragma unroll
            for (int mt = 0; mt < 4; mt++) {
                int rA = wm * 64 + mt * 16 + (lane & 15);
                int cA = ks * 2 + (lane >> 4);
                unsigned addr = aBase + rA * 128 + (((cA ^ (rA & 7))) << 4);
                asm volatile("ldmatrix.sync.aligned.m8n8.x4.shared.b16 "
                             "{%0,%1,%2,%3}, [%4];"
                             : "=r"(af[mt][0]), "=r"(af[mt][1]),
                               "=r"(af[mt][2]), "=r"(af[mt][3]) : "r"(addr));
            }
            #pragma unroll
            for (int pr = 0; pr < 2; pr++) {
                // x4 tiles: n-pair (pr*16..+16), lanes select 8x8 tiles:
                // t0 n0-7/kLo t1 n0-7/kHi t2 n8-15/kLo t3 n8-15/kHi
                int rB = wn * 32 + pr * 16 + ((lane >> 4) & 1) * 8 + (lane & 7);
                int cB = ks * 2 + ((lane >> 3) & 1);
                unsigned addr = bBase + rB * 128 + (((cB ^ (rB & 7))) << 4);
                asm volatile("ldmatrix.sync.aligned.m8n8.x4.shared.b16 "
                             "{%0,%1,%2,%3}, [%4];"
                             : "=r"(bf[pr][0]), "=r"(bf[pr][1]),
                               "=r"(bf[pr][2]), "=r"(bf[pr][3]) : "r"(addr));
            }
            #pragma unroll
            for (int mt = 0; mt < 4; mt++)
                #pragma unroll
                for (int pr = 0; pr < 2; pr++) {
                    asm volatile(
                        "mma.sync.aligned.m16n8k16.row.col.f32.bf16.bf16.f32 "
                        "{%0,%1,%2,%3}, {%4,%5,%6,%7}, {%8,%9}, {%0,%1,%2,%3};"
                        : "+f"(acc[mt][2*pr][0]), "+f"(acc[mt][2*pr][1]),
                          "+f"(acc[mt][2*pr][2]), "+f"(acc[mt][2*pr][3])
                        : "r"(af[mt][0]), "r"(af[mt][1]),
                          "r"(af[mt][2]), "r"(af[mt][3]),
                          "r"(bf[pr][0]), "r"(bf[pr][1]));
                    asm volatile(
                        "mma.sync.aligned.m16n8k16.row.col.f32.bf16.bf16.f32 "
                        "{%0,%1,%2,%3}, {%4,%5,%6,%7}, {%8,%9}, {%0,%1,%2,%3};"
                        : "+f"(acc[mt][2*pr+1][0]), "+f"(acc[mt][2*pr+1][1]),
                          "+f"(acc[mt][2*pr+1][2]), "+f"(acc[mt][2*pr+1][3])
                        : "r"(af[mt][0]), "r"(af[mt][1]),
                          "r"(af[mt][2]), "r"(af[mt][3]),
                          "r"(bf[pr][2]), "r"(bf[pr][3]));
                }
        }
    }

    // ---- epilogue: per-(row, 32-col segment) top-2 -------------------------
    const int gq = lane >> 2;          // row group 0..7
    const int qt = lane & 3;           // col quad 0..3
    float esqv[4][2];
    #pragma unroll
    for (int nt = 0; nt < 4; nt++) {
        int cl = wn * 32 + nt * 8 + qt * 2;
        esqv[nt][0] = s_esq[cl];
        esqv[nt][1] = s_esq[cl + 1];
    }
    const int seg = (colBase + wn * 32) >> 5;

    #pragma unroll
    for (int mt = 0; mt < 4; mt++) {
        int r0 = rowBase + wm * 64 + mt * 16 + gq;
        int r1 = r0 + 8;
        unsigned long long a0 = 0, b0 = 0, a1 = 0, b1 = 0;
        #pragma unroll
        for (int nt = 0; nt < 4; nt++) {
            int cg = colBase + wn * 32 + nt * 8 + qt * 2;
            merge2(a0, b0, pack_score(2.f * acc[mt][nt][0] - esqv[nt][0], cg));
            merge2(a0, b0, pack_score(2.f * acc[mt][nt][1] - esqv[nt][1], cg + 1));
            merge2(a1, b1, pack_score(2.f * acc[mt][nt][2] - esqv[nt][0], cg));
            merge2(a1, b1, pack_score(2.f * acc[mt][nt][3] - esqv[nt][1], cg + 1));
        }
        #pragma unroll
        for (int off = 1; off <= 2; off <<= 1) {
            unsigned long long xa0 = __shfl_xor_sync(0xffffffffu, a0, off);
            unsigned long long xb0 = __shfl_xor_sync(0xffffffffu, b0, off);
            unsigned long long xa1 = __shfl_xor_sync(0xffffffffu, a1, off);
            unsigned long long xb1 = __shfl_xor_sync(0xffffffffu, b1, off);
            merge2(a0, b0, xa0); merge2(a0, b0, xb0);
            merge2(a1, b1, xa1); merge2(a1, b1, xb1);
        }
        if (qt == 0) {
            g_cand[(size_t)r0 * CPR + seg * 2]     = a0;
            g_cand[(size_t)r0 * CPR + seg * 2 + 1] = b0;
            g_cand[(size_t)r1 * CPR + seg * 2]     = a1;
            g_cand[(size_t)r1 * CPR + seg * 2 + 1] = b1;
        }
    }
}

// ---------------- kernel 3: exact fp32 rescore + gather --------------------
__global__ void vq_rescore(const float* __restrict__ x, const float* __restrict__ embed,
                           float* __restrict__ out, int write_idx) {
    const int row = blockIdx.x, tid = threadIdx.x;   // 128 threads
    const int wid = tid >> 5, lid = tid & 31;
    __shared__ unsigned long long s_max4[4];
    __shared__ int s_cnt;
    __shared__ int s_idx[64];
    __shared__ float s_red[4];
    __shared__ unsigned long long s_win;
    if (tid == 0) s_cnt = 0;

    const unsigned long long* cd = g_cand + (size_t)row * CPR;
    unsigned long long m = 0;
    #pragma unroll
    for (int i = tid; i < CPR; i += 128) m = max(m, cd[i]);
    #pragma unroll
    for (int o = 16; o > 0; o >>= 1)
        m = max(m, __shfl_down_sync(0xffffffffu, m, o));
    if (lid == 0) s_max4[wid] = m;
    __syncthreads();
    m = max(max(s_max4[0], s_max4[1]), max(s_max4[2], s_max4[3]));
    const float thr = unpack_score(m) - EPSF;

    for (int i = tid; i < CPR; i += 128) {
        unsigned long long p = cd[i];
        if (unpack_score(p) >= thr) {
            int k = atomicAdd(&s_cnt, 1);
            if (k < 64) s_idx[k] = unpack_idx(p);
        }
    }
    __syncthreads();
    const int cnt = min(s_cnt, 64);

    const float4 xv = ((const float4*)(x + (size_t)row * DIMV))[tid];
    unsigned long long best = 0ULL;
    for (int c = 0; c < cnt; c++) {
        const int idx = s_idx[c];
        float4 ev = ((const float4*)(embed + (size_t)idx * DIMV))[tid];
        float d = xv.x * ev.x + xv.y * ev.y + xv.z * ev.z + xv.w * ev.w;
        #pragma unroll
        for (int o = 16; o > 0; o >>= 1) d += __shfl_down_sync(0xffffffffu, d, o);
        if (lid == 0) s_red[wid] = d;
        __syncthreads();
        if (tid == 0) {
            float dot = s_red[0] + s_red[1] + s_red[2] + s_red[3];
            unsigned long long p = pack_score(2.0f * dot - g_esq[idx], idx);
            if (p > best) best = p;
        }
        __syncthreads();
    }
    if (tid == 0) s_win = best;
    __syncthreads();

    const int widx = unpack_idx(s_win);
    float4 ev = ((const float4*)(embed + (size_t)widx * DIMV))[tid];
    ((float4*)(out + (size_t)row * DIMV))[tid] = ev;
    if (write_idx && tid == 0)
        out[(size_t)NROWS * DIMV + row] = (float)widx;
}

// ---------------- launch ----------------------------------------------------
extern "C" void kernel_launch(void* const* d_in, const int* in_sizes, int n_in,
                              void* d_out, int out_size) {
    const float* x     = (const float*)d_in[0];
    const float* embed = (const float*)d_in[1];
    float* out = (float*)d_out;

    cudaFuncSetAttribute(vq_gemm, cudaFuncAttributeMaxDynamicSharedMemorySize,
                         NSTAGE * STAGE_BYTES);

    vq_prep<<<NROWS, 128>>>(x, embed);

    dim3 grid(KCODES / BN, NROWS / BM);   // 32 x 128
    vq_gemm<<<grid, NTHR, NSTAGE * STAGE_BYTES>>>();

    int write_idx = (out_size >= NROWS * DIMV + NROWS) ? 1 : 0;
    vq_rescore<<<NROWS, 128>>>(x, embed, out, write_idx);
}

// round 7
// speedup vs baseline: 2.0705x; 1.0446x over previous
#include <cuda_runtime.h>
#include <cuda_bf16.h>

#define DIMV   512
#define NROWS  16384
#define KCODES 8192

#define BM 128
#define BN 128
#define BK 64
#define NCHUNK (DIMV / BK)        // 8
#define NSTAGE 3
#define STAGE_BYTES 32768         // A 16KB + B 16KB
#define NSEG  (KCODES / 32)       // 256 segments of 32 codes
#define CPR   (NSEG * 2)          // 512 candidate slots per row
#define EPSF  1.0f

// ---------------- device globals (no runtime allocation allowed) ----------
__device__ __align__(16) __nv_bfloat16 g_xb[(size_t)NROWS * DIMV];
__device__ __align__(16) __nv_bfloat16 g_eb[(size_t)KCODES * DIMV];
__device__ float g_esq[KCODES];
__device__ unsigned long long g_cand[(size_t)NROWS * CPR];

// ---------------- packing: monotonic (score, smaller-idx-wins) ------------
__device__ __forceinline__ unsigned long long pack_score(float s, int idx) {
    unsigned u = __float_as_uint(s);
    u = (u & 0x80000000u) ? ~u : (u | 0x80000000u);
    return ((unsigned long long)u << 32) | (unsigned)(KCODES - 1 - idx);
}
__device__ __forceinline__ float unpack_score(unsigned long long p) {
    unsigned u = (unsigned)(p >> 32);
    u = (u & 0x80000000u) ? (u ^ 0x80000000u) : ~u;
    return __uint_as_float(u);
}
__device__ __forceinline__ int unpack_idx(unsigned long long p) {
    return KCODES - 1 - (int)(unsigned)(p & 0xFFFFFFFFu);
}
__device__ __forceinline__ void merge2(unsigned long long& a, unsigned long long& b,
                                       unsigned long long p) {
    if (p > a) { b = a; a = p; } else if (p > b) { b = p; }
}
__device__ __forceinline__ unsigned smem_u32(const void* p) {
    unsigned a;
    asm("{ .reg .u64 t; cvta.to.shared.u64 t, %1; cvt.u32.u64 %0, t; }"
        : "=r"(a) : "l"(p));
    return a;
}

// ---------------- kernel 1: bf16 conversion + |e|^2 ------------------------
__global__ void vq_prep(const float* __restrict__ x, const float* __restrict__ embed) {
    int b = blockIdx.x, tid = threadIdx.x;   // NROWS blocks x 128 threads
    float4 v = ((const float4*)(x + (size_t)b * DIMV))[tid];
    __nv_bfloat162 p0, p1;
    p0.x = __float2bfloat16(v.x); p0.y = __float2bfloat16(v.y);
    p1.x = __float2bfloat16(v.z); p1.y = __float2bfloat16(v.w);
    uint2 pk = make_uint2(*(unsigned*)&p0, *(unsigned*)&p1);
    *(uint2*)(g_xb + (size_t)b * DIMV + tid * 4) = pk;

    if (b < KCODES) {
        float4 e = ((const float4*)(embed + (size_t)b * DIMV))[tid];
        __nv_bfloat162 q0, q1;
        q0.x = __float2bfloat16(e.x); q0.y = __float2bfloat16(e.y);
        q1.x = __float2bfloat16(e.z); q1.y = __float2bfloat16(e.w);
        uint2 qk = make_uint2(*(unsigned*)&q0, *(unsigned*)&q1);
        *(uint2*)(g_eb + (size_t)b * DIMV + tid * 4) = qk;

        float s = e.x * e.x + e.y * e.y + e.z * e.z + e.w * e.w;
        #pragma unroll
        for (int o = 16; o > 0; o >>= 1) s += __shfl_down_sync(0xffffffffu, s, o);
        __shared__ float red[4];
        if ((tid & 31) == 0) red[tid >> 5] = s;
        __syncthreads();
        if (tid == 0) g_esq[b] = red[0] + red[1] + red[2] + red[3];
    }
}

// ---------------- kernel 2: bf16 HMMA GEMM, CTA 128x128, 3-stage -----------
// 256 threads, warp grid 2x4, warp tile 64x32, 2 CTAs/SM, 1 sync per chunk.
__global__ __launch_bounds__(256, 2)
void vq_gemm() {
    extern __shared__ char smem[];                // 3 stages x (A 16KB + B 16KB)
    __shared__ float s_esq[BN];

    const int tid = threadIdx.x, lane = tid & 31, wid = tid >> 5;
    const int wm = wid >> 2, wn = wid & 3;        // 2 x 4 warp grid
    const int rowBase = blockIdx.y * BM;
    const int colBase = blockIdx.x * BN;
    const unsigned sb = smem_u32(smem);

    if (tid < BN) s_esq[tid] = g_esq[colBase + tid];

    float acc[4][4][4];
    #pragma unroll
    for (int mt = 0; mt < 4; mt++)
        #pragma unroll
        for (int nt = 0; nt < 4; nt++)
            #pragma unroll
            for (int q = 0; q < 4; q++) acc[mt][nt][q] = 0.f;

    // stage loader: A 128x64, B 128x64 bf16, XOR-swizzled 128B rows
    #define ISSUE_STAGE(c) do {                                              \
        const unsigned _aB = sb + ((c) % NSTAGE) * STAGE_BYTES;              \
        const unsigned _bB = _aB + 16384u;                                   \
        const __nv_bfloat16* _xp = g_xb + (size_t)rowBase * DIMV + (c) * BK; \
        const __nv_bfloat16* _ep = g_eb + (size_t)colBase * DIMV + (c) * BK; \
        _Pragma("unroll")                                                    \
        for (int _it = 0; _it < 4; _it++) {                                  \
            int _u = tid + _it * 256;                                        \
            int _r = _u >> 3, _c = _u & 7;                                   \
            unsigned _off = _r * 128 + (((_c ^ (_r & 7))) << 4);             \
            asm volatile("cp.async.cg.shared.global [%0], [%1], 16;"         \
                :: "r"(_aB + _off), "l"(_xp + (size_t)_r * DIMV + _c * 8));  \
            asm volatile("cp.async.cg.shared.global [%0], [%1], 16;"         \
                :: "r"(_bB + _off), "l"(_ep + (size_t)_r * DIMV + _c * 8));  \
        }                                                                    \
        asm volatile("cp.async.commit_group;");                              \
    } while (0)

    ISSUE_STAGE(0);
    ISSUE_STAGE(1);

    #pragma unroll 1
    for (int c = 0; c < NCHUNK; c++) {
        if (c < NCHUNK - 1) asm volatile("cp.async.wait_group 1;");
        else                asm volatile("cp.async.wait_group 0;");
        __syncthreads();
        // after the barrier, buffer (c+2)%3 == (c-1)%3 is dead: safe to refill
        if (c + 2 < NCHUNK) ISSUE_STAGE(c + 2);

        const unsigned aBase = sb + (c % NSTAGE) * STAGE_BYTES;
        const unsigned bBase = aBase + 16384u;

        #pragma unroll
        for (int ks = 0; ks < 4; ks++) {
            unsigned af[4][4], bf[2][4];
            #pragma unroll
            for (int mt = 0; mt < 4; mt++) {
                int rA = wm * 64 + mt * 16 + (lane & 15);
                int cA = ks * 2 + (lane >> 4);
                unsigned addr = aBase + rA * 128 + (((cA ^ (rA & 7))) << 4);
                asm volatile("ldmatrix.sync.aligned.m8n8.x4.shared.b16 "
                             "{%0,%1,%2,%3}, [%4];"
                             : "=r"(af[mt][0]), "=r"(af[mt][1]),
                               "=r"(af[mt][2]), "=r"(af[mt][3]) : "r"(addr));
            }
            #pragma unroll
            for (int pr = 0; pr < 2; pr++) {
                // x4 tiles: t0 n0-7/kLo t1 n0-7/kHi t2 n8-15/kLo t3 n8-15/kHi
                int rB = wn * 32 + pr * 16 + ((lane >> 4) & 1) * 8 + (lane & 7);
                int cB = ks * 2 + ((lane >> 3) & 1);
                unsigned addr = bBase + rB * 128 + (((cB ^ (rB & 7))) << 4);
                asm volatile("ldmatrix.sync.aligned.m8n8.x4.shared.b16 "
                             "{%0,%1,%2,%3}, [%4];"
                             : "=r"(bf[pr][0]), "=r"(bf[pr][1]),
                               "=r"(bf[pr][2]), "=r"(bf[pr][3]) : "r"(addr));
            }
            #pragma unroll
            for (int mt = 0; mt < 4; mt++)
                #pragma unroll
                for (int pr = 0; pr < 2; pr++) {
                    asm volatile(
                        "mma.sync.aligned.m16n8k16.row.col.f32.bf16.bf16.f32 "
                        "{%0,%1,%2,%3}, {%4,%5,%6,%7}, {%8,%9}, {%0,%1,%2,%3};"
                        : "+f"(acc[mt][2*pr][0]), "+f"(acc[mt][2*pr][1]),
                          "+f"(acc[mt][2*pr][2]), "+f"(acc[mt][2*pr][3])
                        : "r"(af[mt][0]), "r"(af[mt][1]),
                          "r"(af[mt][2]), "r"(af[mt][3]),
                          "r"(bf[pr][0]), "r"(bf[pr][1]));
                    asm volatile(
                        "mma.sync.aligned.m16n8k16.row.col.f32.bf16.bf16.f32 "
                        "{%0,%1,%2,%3}, {%4,%5,%6,%7}, {%8,%9}, {%0,%1,%2,%3};"
                        : "+f"(acc[mt][2*pr+1][0]), "+f"(acc[mt][2*pr+1][1]),
                          "+f"(acc[mt][2*pr+1][2]), "+f"(acc[mt][2*pr+1][3])
                        : "r"(af[mt][0]), "r"(af[mt][1]),
                          "r"(af[mt][2]), "r"(af[mt][3]),
                          "r"(bf[pr][2]), "r"(bf[pr][3]));
                }
        }
    }

    // ---- epilogue: per-(row, 32-col segment) top-2 -------------------------
    const int gq = lane >> 2;          // row group 0..7
    const int qt = lane & 3;           // col quad 0..3
    float esqv[4][2];
    #pragma unroll
    for (int nt = 0; nt < 4; nt++) {
        int cl = wn * 32 + nt * 8 + qt * 2;
        esqv[nt][0] = s_esq[cl];
        esqv[nt][1] = s_esq[cl + 1];
    }
    const int seg = (colBase + wn * 32) >> 5;

    #pragma unroll
    for (int mt = 0; mt < 4; mt++) {
        int r0 = rowBase + wm * 64 + mt * 16 + gq;
        int r1 = r0 + 8;
        unsigned long long a0 = 0, b0 = 0, a1 = 0, b1 = 0;
        #pragma unroll
        for (int nt = 0; nt < 4; nt++) {
            int cg = colBase + wn * 32 + nt * 8 + qt * 2;
            merge2(a0, b0, pack_score(2.f * acc[mt][nt][0] - esqv[nt][0], cg));
            merge2(a0, b0, pack_score(2.f * acc[mt][nt][1] - esqv[nt][1], cg + 1));
            merge2(a1, b1, pack_score(2.f * acc[mt][nt][2] - esqv[nt][0], cg));
            merge2(a1, b1, pack_score(2.f * acc[mt][nt][3] - esqv[nt][1], cg + 1));
        }
        #pragma unroll
        for (int off = 1; off <= 2; off <<= 1) {
            unsigned long long xa0 = __shfl_xor_sync(0xffffffffu, a0, off);
            unsigned long long xb0 = __shfl_xor_sync(0xffffffffu, b0, off);
            unsigned long long xa1 = __shfl_xor_sync(0xffffffffu, a1, off);
            unsigned long long xb1 = __shfl_xor_sync(0xffffffffu, b1, off);
            merge2(a0, b0, xa0); merge2(a0, b0, xb0);
            merge2(a1, b1, xa1); merge2(a1, b1, xb1);
        }
        if (qt == 0) {
            g_cand[(size_t)r0 * CPR + seg * 2]     = a0;
            g_cand[(size_t)r0 * CPR + seg * 2 + 1] = b0;
            g_cand[(size_t)r1 * CPR + seg * 2]     = a1;
            g_cand[(size_t)r1 * CPR + seg * 2 + 1] = b1;
        }
    }
}

// ---------------- kernel 3: exact fp32 rescore + gather --------------------
__global__ void vq_rescore(const float* __restrict__ x, const float* __restrict__ embed,
                           float* __restrict__ out, int write_idx) {
    const int row = blockIdx.x, tid = threadIdx.x;   // 128 threads
    const int wid = tid >> 5, lid = tid & 31;
    __shared__ unsigned long long s_max4[4];
    __shared__ int s_cnt;
    __shared__ int s_idx[64];
    __shared__ float s_red[4];
    __shared__ unsigned long long s_win;
    if (tid == 0) s_cnt = 0;

    const unsigned long long* cd = g_cand + (size_t)row * CPR;
    unsigned long long m = 0;
    #pragma unroll
    for (int i = tid; i < CPR; i += 128) m = max(m, cd[i]);
    #pragma unroll
    for (int o = 16; o > 0; o >>= 1)
        m = max(m, __shfl_down_sync(0xffffffffu, m, o));
    if (lid == 0) s_max4[wid] = m;
    __syncthreads();
    m = max(max(s_max4[0], s_max4[1]), max(s_max4[2], s_max4[3]));
    const float thr = unpack_score(m) - EPSF;

    for (int i = tid; i < CPR; i += 128) {
        unsigned long long p = cd[i];
        if (unpack_score(p) >= thr) {
            int k = atomicAdd(&s_cnt, 1);
            if (k < 64) s_idx[k] = unpack_idx(p);
        }
    }
    __syncthreads();
    const int cnt = min(s_cnt, 64);

    const float4 xv = ((const float4*)(x + (size_t)row * DIMV))[tid];
    unsigned long long best = 0ULL;
    for (int c = 0; c < cnt; c++) {
        const int idx = s_idx[c];
        float4 ev = ((const float4*)(embed + (size_t)idx * DIMV))[tid];
        float d = xv.x * ev.x + xv.y * ev.y + xv.z * ev.z + xv.w * ev.w;
        #pragma unroll
        for (int o = 16; o > 0; o >>= 1) d += __shfl_down_sync(0xffffffffu, d, o);
        if (lid == 0) s_red[wid] = d;
        __syncthreads();
        if (tid == 0) {
            float dot = s_red[0] + s_red[1] + s_red[2] + s_red[3];
            unsigned long long p = pack_score(2.0f * dot - g_esq[idx], idx);
            if (p > best) best = p;
        }
        __syncthreads();
    }
    if (tid == 0) s_win = best;
    __syncthreads();

    const int widx = unpack_idx(s_win);
    float4 ev = ((const float4*)(embed + (size_t)widx * DIMV))[tid];
    ((float4*)(out + (size_t)row * DIMV))[tid] = ev;
    if (write_idx && tid == 0)
        out[(size_t)NROWS * DIMV + row] = (float)widx;
}

// ---------------- launch ----------------------------------------------------
extern "C" void kernel_launch(void* const* d_in, const int* in_sizes, int n_in,
                              void* d_out, int out_size) {
    const float* x     = (const float*)d_in[0];
    const float* embed = (const float*)d_in[1];
    float* out = (float*)d_out;

    cudaFuncSetAttribute(vq_gemm, cudaFuncAttributeMaxDynamicSharedMemorySize,
                         NSTAGE * STAGE_BYTES);

    vq_prep<<<NROWS, 128>>>(x, embed);

    dim3 grid(KCODES / BN, NROWS / BM);   // 64 x 128
    vq_gemm<<<grid, 256, NSTAGE * STAGE_BYTES>>>();

    int write_idx = (out_size >= NROWS * DIMV + NROWS) ? 1 : 0;
    vq_rescore<<<NROWS, 128>>>(x, embed, out, write_idx);
}

// round 8
// speedup vs baseline: 2.1774x; 1.0516x over previous
#include <cuda_runtime.h>
#include <cuda_bf16.h>

#define DIMV   512
#define NROWS  16384
#define KCODES 8192

#define BM 128
#define BN 128
#define BK 64
#define NCHUNK (DIMV / BK)        // 8
#define NSEG  (KCODES / 32)       // 256 segments of 32 codes
#define CPR   (NSEG * 2)          // 512 candidate slots per row
#define EPSF  1.0f

// ---------------- device globals (no runtime allocation allowed) ----------
__device__ __align__(16) __nv_bfloat16 g_xb[(size_t)NROWS * DIMV];
__device__ __align__(16) __nv_bfloat16 g_eb[(size_t)KCODES * DIMV];
__device__ float g_esq[KCODES];
__device__ unsigned long long g_cand[(size_t)NROWS * CPR];

// ---------------- packing: monotonic (score, smaller-idx-wins) ------------
__device__ __forceinline__ unsigned long long pack_score(float s, int idx) {
    unsigned u = __float_as_uint(s);
    u = (u & 0x80000000u) ? ~u : (u | 0x80000000u);
    return ((unsigned long long)u << 32) | (unsigned)(KCODES - 1 - idx);
}
__device__ __forceinline__ float unpack_score(unsigned long long p) {
    unsigned u = (unsigned)(p >> 32);
    u = (u & 0x80000000u) ? (u ^ 0x80000000u) : ~u;
    return __uint_as_float(u);
}
__device__ __forceinline__ int unpack_idx(unsigned long long p) {
    return KCODES - 1 - (int)(unsigned)(p & 0xFFFFFFFFu);
}
__device__ __forceinline__ void merge2(unsigned long long& a, unsigned long long& b,
                                       unsigned long long p) {
    if (p > a) { b = a; a = p; } else if (p > b) { b = p; }
}
__device__ __forceinline__ unsigned smem_u32(const void* p) {
    unsigned a;
    asm("{ .reg .u64 t; cvta.to.shared.u64 t, %1; cvt.u32.u64 %0, t; }"
        : "=r"(a) : "l"(p));
    return a;
}

// ---------------- kernel 1: bf16 conversion + |e|^2 ------------------------
__global__ void vq_prep(const float* __restrict__ x, const float* __restrict__ embed) {
    int b = blockIdx.x, tid = threadIdx.x;   // NROWS blocks x 128 threads
    float4 v = ((const float4*)(x + (size_t)b * DIMV))[tid];
    __nv_bfloat162 p0, p1;
    p0.x = __float2bfloat16(v.x); p0.y = __float2bfloat16(v.y);
    p1.x = __float2bfloat16(v.z); p1.y = __float2bfloat16(v.w);
    uint2 pk = make_uint2(*(unsigned*)&p0, *(unsigned*)&p1);
    *(uint2*)(g_xb + (size_t)b * DIMV + tid * 4) = pk;

    if (b < KCODES) {
        float4 e = ((const float4*)(embed + (size_t)b * DIMV))[tid];
        __nv_bfloat162 q0, q1;
        q0.x = __float2bfloat16(e.x); q0.y = __float2bfloat16(e.y);
        q1.x = __float2bfloat16(e.z); q1.y = __float2bfloat16(e.w);
        uint2 qk = make_uint2(*(unsigned*)&q0, *(unsigned*)&q1);
        *(uint2*)(g_eb + (size_t)b * DIMV + tid * 4) = qk;

        float s = e.x * e.x + e.y * e.y + e.z * e.z + e.w * e.w;
        #pragma unroll
        for (int o = 16; o > 0; o >>= 1) s += __shfl_down_sync(0xffffffffu, s, o);
        __shared__ float red[4];
        if ((tid & 31) == 0) red[tid >> 5] = s;
        __syncthreads();
        if (tid == 0) g_esq[b] = red[0] + red[1] + red[2] + red[3];
    }
}

// ---------------- kernel 2: bf16 HMMA GEMM + top-2-per-segment epilogue ----
// CTA 128x128, BK=64, 256 threads, warp grid 2x4, warp tile 64x32,
// 2 CTAs/SM, 2-stage cp.async; ks-level fragment double-buffering.
__global__ __launch_bounds__(256, 2)
void vq_gemm() {
    extern __shared__ char smem[];                // A0,B0,A1,B1: 4 x 16KB
    __shared__ float s_esq[BN];

    const int tid = threadIdx.x, lane = tid & 31, wid = tid >> 5;
    const int wm = wid >> 2, wn = wid & 3;
    const int rowBase = blockIdx.y * BM;
    const int colBase = blockIdx.x * BN;
    const unsigned sb = smem_u32(smem);

    if (tid < BN) s_esq[tid] = g_esq[colBase + tid];

    float acc[4][4][4];
    #pragma unroll
    for (int mt = 0; mt < 4; mt++)
        #pragma unroll
        for (int nt = 0; nt < 4; nt++)
            #pragma unroll
            for (int q = 0; q < 4; q++) acc[mt][nt][q] = 0.f;

    // cp.async tile loader: 128 rows x 8 chunks(16B) per operand, swizzled
    #define ISSUE_CHUNK(c) do {                                              \
        const int _buf = (c) & 1;                                            \
        const unsigned _aB = sb + _buf * 32768u;                             \
        const unsigned _bB = _aB + 16384u;                                   \
        const __nv_bfloat16* _xp = g_xb + (size_t)rowBase * DIMV + (c) * BK; \
        const __nv_bfloat16* _ep = g_eb + (size_t)colBase * DIMV + (c) * BK; \
        _Pragma("unroll")                                                    \
        for (int _it = 0; _it < 4; _it++) {                                  \
            int _u = tid + _it * 256;                                        \
            int _r = _u >> 3, _c = _u & 7;                                   \
            unsigned _off = _r * 128 + (((_c ^ (_r & 7))) << 4);             \
            asm volatile("cp.async.cg.shared.global [%0], [%1], 16;"         \
                :: "r"(_aB + _off), "l"(_xp + (size_t)_r * DIMV + _c * 8));  \
            asm volatile("cp.async.cg.shared.global [%0], [%1], 16;"         \
                :: "r"(_bB + _off), "l"(_ep + (size_t)_r * DIMV + _c * 8));  \
        }                                                                    \
        asm volatile("cp.async.commit_group;");                              \
    } while (0)

    // fragment loads for one ks step into buffer set s
    #define LOAD_FRAGS(ks, s) do {                                           \
        _Pragma("unroll")                                                    \
        for (int _mt = 0; _mt < 4; _mt++) {                                  \
            int rA = wm * 64 + _mt * 16 + (lane & 15);                       \
            int cA = (ks) * 2 + (lane >> 4);                                 \
            unsigned addr = aBase + rA * 128 + (((cA ^ (rA & 7))) << 4);     \
            asm volatile("ldmatrix.sync.aligned.m8n8.x4.shared.b16 "         \
                         "{%0,%1,%2,%3}, [%4];"                              \
                         : "=r"(af[s][_mt][0]), "=r"(af[s][_mt][1]),         \
                           "=r"(af[s][_mt][2]), "=r"(af[s][_mt][3])          \
                         : "r"(addr));                                       \
        }                                                                    \
        _Pragma("unroll")                                                    \
        for (int _nt = 0; _nt < 4; _nt++) {                                  \
            int rB = wn * 32 + _nt * 8 + (lane & 7);                         \
            int cB = (ks) * 2 + ((lane >> 3) & 1);                           \
            unsigned addr = bBase + rB * 128 + (((cB ^ (rB & 7))) << 4);     \
            asm volatile("ldmatrix.sync.aligned.m8n8.x2.shared.b16 "         \
                         "{%0,%1}, [%2];"                                    \
                         : "=r"(bf[s][_nt][0]), "=r"(bf[s][_nt][1])          \
                         : "r"(addr));                                       \
        }                                                                    \
    } while (0)

    ISSUE_CHUNK(0);

    #pragma unroll 1
    for (int c = 0; c < NCHUNK; c++) {
        if (c < NCHUNK - 1) {
            ISSUE_CHUNK(c + 1);
            asm volatile("cp.async.wait_group 1;");
        } else {
            asm volatile("cp.async.wait_group 0;");
        }
        __syncthreads();

        const unsigned aBase = sb + (c & 1) * 32768u;
        const unsigned bBase = aBase + 16384u;

        unsigned af[2][4][4], bf[2][4][2];
        LOAD_FRAGS(0, 0);

        #pragma unroll
        for (int ks = 0; ks < 4; ks++) {
            const int cur = ks & 1, nxt = cur ^ 1;
            if (ks < 3) LOAD_FRAGS(ks + 1, nxt);
            #pragma unroll
            for (int mt = 0; mt < 4; mt++)
                #pragma unroll
                for (int nt = 0; nt < 4; nt++)
                    asm volatile(
                        "mma.sync.aligned.m16n8k16.row.col.f32.bf16.bf16.f32 "
                        "{%0,%1,%2,%3}, {%4,%5,%6,%7}, {%8,%9}, {%0,%1,%2,%3};"
                        : "+f"(acc[mt][nt][0]), "+f"(acc[mt][nt][1]),
                          "+f"(acc[mt][nt][2]), "+f"(acc[mt][nt][3])
                        : "r"(af[cur][mt][0]), "r"(af[cur][mt][1]),
                          "r"(af[cur][mt][2]), "r"(af[cur][mt][3]),
                          "r"(bf[cur][nt][0]), "r"(bf[cur][nt][1]));
        }
        __syncthreads();
    }

    // ---- epilogue: per-(row, 32-col segment) top-2 -------------------------
    const int gq = lane >> 2;          // row group 0..7
    const int qt = lane & 3;           // col quad 0..3
    float esqv[4][2];
    #pragma unroll
    for (int nt = 0; nt < 4; nt++) {
        int cl = wn * 32 + nt * 8 + qt * 2;
        esqv[nt][0] = s_esq[cl];
        esqv[nt][1] = s_esq[cl + 1];
    }
    const int seg = (colBase + wn * 32) >> 5;

    #pragma unroll
    for (int mt = 0; mt < 4; mt++) {
        int r0 = rowBase + wm * 64 + mt * 16 + gq;
        int r1 = r0 + 8;
        unsigned long long a0 = 0, b0 = 0, a1 = 0, b1 = 0;
        #pragma unroll
        for (int nt = 0; nt < 4; nt++) {
            int cg = colBase + wn * 32 + nt * 8 + qt * 2;
            merge2(a0, b0, pack_score(2.f * acc[mt][nt][0] - esqv[nt][0], cg));
            merge2(a0, b0, pack_score(2.f * acc[mt][nt][1] - esqv[nt][1], cg + 1));
            merge2(a1, b1, pack_score(2.f * acc[mt][nt][2] - esqv[nt][0], cg));
            merge2(a1, b1, pack_score(2.f * acc[mt][nt][3] - esqv[nt][1], cg + 1));
        }
        #pragma unroll
        for (int off = 1; off <= 2; off <<= 1) {
            unsigned long long xa0 = __shfl_xor_sync(0xffffffffu, a0, off);
            unsigned long long xb0 = __shfl_xor_sync(0xffffffffu, b0, off);
            unsigned long long xa1 = __shfl_xor_sync(0xffffffffu, a1, off);
            unsigned long long xb1 = __shfl_xor_sync(0xffffffffu, b1, off);
            merge2(a0, b0, xa0); merge2(a0, b0, xb0);
            merge2(a1, b1, xa1); merge2(a1, b1, xb1);
        }
        if (qt == 0) {
            g_cand[(size_t)r0 * CPR + seg * 2]     = a0;
            g_cand[(size_t)r0 * CPR + seg * 2 + 1] = b0;
            g_cand[(size_t)r1 * CPR + seg * 2]     = a1;
            g_cand[(size_t)r1 * CPR + seg * 2 + 1] = b1;
        }
    }
}

// ---------------- kernel 3: exact fp32 rescore + gather --------------------
__global__ void vq_rescore(const float* __restrict__ x, const float* __restrict__ embed,
                           float* __restrict__ out, int write_idx) {
    const int row = blockIdx.x, tid = threadIdx.x;   // 128 threads
    const int wid = tid >> 5, lid = tid & 31;
    __shared__ unsigned long long s_max4[4];
    __shared__ int s_cnt;
    __shared__ int s_idx[64];
    __shared__ float s_red[4];
    __shared__ unsigned long long s_win;
    if (tid == 0) s_cnt = 0;

    const unsigned long long* cd = g_cand + (size_t)row * CPR;
    unsigned long long m = 0;
    #pragma unroll
    for (int i = tid; i < CPR; i += 128) m = max(m, cd[i]);
    #pragma unroll
    for (int o = 16; o > 0; o >>= 1)
        m = max(m, __shfl_down_sync(0xffffffffu, m, o));
    if (lid == 0) s_max4[wid] = m;
    __syncthreads();
    m = max(max(s_max4[0], s_max4[1]), max(s_max4[2], s_max4[3]));
    const float thr = unpack_score(m) - EPSF;

    for (int i = tid; i < CPR; i += 128) {
        unsigned long long p = cd[i];
        if (unpack_score(p) >= thr) {
            int k = atomicAdd(&s_cnt, 1);
            if (k < 64) s_idx[k] = unpack_idx(p);
        }
    }
    __syncthreads();
    const int cnt = min(s_cnt, 64);

    const float4 xv = ((const float4*)(x + (size_t)row * DIMV))[tid];
    unsigned long long best = 0ULL;
    for (int c = 0; c < cnt; c++) {
        const int idx = s_idx[c];
        float4 ev = ((const float4*)(embed + (size_t)idx * DIMV))[tid];
        float d = xv.x * ev.x + xv.y * ev.y + xv.z * ev.z + xv.w * ev.w;
        #pragma unroll
        for (int o = 16; o > 0; o >>= 1) d += __shfl_down_sync(0xffffffffu, d, o);
        if (lid == 0) s_red[wid] = d;
        __syncthreads();
        if (tid == 0) {
            float dot = s_red[0] + s_red[1] + s_red[2] + s_red[3];
            unsigned long long p = pack_score(2.0f * dot - g_esq[idx], idx);
            if (p > best) best = p;
        }
        __syncthreads();
    }
    if (tid == 0) s_win = best;
    __syncthreads();

    const int widx = unpack_idx(s_win);
    float4 ev = ((const float4*)(embed + (size_t)widx * DIMV))[tid];
    ((float4*)(out + (size_t)row * DIMV))[tid] = ev;
    if (write_idx && tid == 0)
        out[(size_t)NROWS * DIMV + row] = (float)widx;
}

// ---------------- launch ----------------------------------------------------
extern "C" void kernel_launch(void* const* d_in, const int* in_sizes, int n_in,
                              void* d_out, int out_size) {
    const float* x     = (const float*)d_in[0];
    const float* embed = (const float*)d_in[1];
    float* out = (float*)d_out;

    cudaFuncSetAttribute(vq_gemm, cudaFuncAttributeMaxDynamicSharedMemorySize, 65536);

    vq_prep<<<NROWS, 128>>>(x, embed);

    dim3 grid(KCODES / BN, NROWS / BM);   // 64 x 128
    vq_gemm<<<grid, 256, 65536>>>();

    int write_idx = (out_size >= NROWS * DIMV + NROWS) ? 1 : 0;
    vq_rescore<<<NROWS, 128>>>(x, embed, out, write_idx);
}

// round 9
// speedup vs baseline: 2.2383x; 1.0280x over previous
#include <cuda_runtime.h>
#include <cuda_bf16.h>

#define DIMV   512
#define NROWS  16384
#define KCODES 8192

#define BM 128
#define BN 128
#define BK 64
#define NCHUNK (DIMV / BK)        // 8
#define NSEG  (KCODES / 32)       // 256 segments of 32 codes
#define CPR   (NSEG * 2)          // 512 candidate slots per row
#define EPSF  1.0f
#define MAXCAND 32

// ---------------- device globals (no runtime allocation allowed) ----------
__device__ __align__(16) __nv_bfloat16 g_xb[(size_t)NROWS * DIMV];
__device__ __align__(16) __nv_bfloat16 g_eb[(size_t)KCODES * DIMV];
__device__ float g_esq[KCODES];
__device__ unsigned long long g_cand[(size_t)NROWS * CPR];

// ---------------- packing: monotonic (score, smaller-idx-wins) ------------
__device__ __forceinline__ unsigned long long pack_score(float s, int idx) {
    unsigned u = __float_as_uint(s);
    u = (u & 0x80000000u) ? ~u : (u | 0x80000000u);
    return ((unsigned long long)u << 32) | (unsigned)(KCODES - 1 - idx);
}
__device__ __forceinline__ float unpack_score(unsigned long long p) {
    unsigned u = (unsigned)(p >> 32);
    u = (u & 0x80000000u) ? (u ^ 0x80000000u) : ~u;
    return __uint_as_float(u);
}
__device__ __forceinline__ int unpack_idx(unsigned long long p) {
    return KCODES - 1 - (int)(unsigned)(p & 0xFFFFFFFFu);
}
__device__ __forceinline__ void merge2(unsigned long long& a, unsigned long long& b,
                                       unsigned long long p) {
    if (p > a) { b = a; a = p; } else if (p > b) { b = p; }
}
__device__ __forceinline__ unsigned smem_u32(const void* p) {
    unsigned a;
    asm("{ .reg .u64 t; cvta.to.shared.u64 t, %1; cvt.u32.u64 %0, t; }"
        : "=r"(a) : "l"(p));
    return a;
}

// ---------------- kernel 1: bf16 conversion + |e|^2 ------------------------
__global__ void vq_prep(const float* __restrict__ x, const float* __restrict__ embed) {
    int b = blockIdx.x, tid = threadIdx.x;   // NROWS blocks x 128 threads
    float4 v = ((const float4*)(x + (size_t)b * DIMV))[tid];
    __nv_bfloat162 p0, p1;
    p0.x = __float2bfloat16(v.x); p0.y = __float2bfloat16(v.y);
    p1.x = __float2bfloat16(v.z); p1.y = __float2bfloat16(v.w);
    uint2 pk = make_uint2(*(unsigned*)&p0, *(unsigned*)&p1);
    *(uint2*)(g_xb + (size_t)b * DIMV + tid * 4) = pk;

    if (b < KCODES) {
        float4 e = ((const float4*)(embed + (size_t)b * DIMV))[tid];
        __nv_bfloat162 q0, q1;
        q0.x = __float2bfloat16(e.x); q0.y = __float2bfloat16(e.y);
        q1.x = __float2bfloat16(e.z); q1.y = __float2bfloat16(e.w);
        uint2 qk = make_uint2(*(unsigned*)&q0, *(unsigned*)&q1);
        *(uint2*)(g_eb + (size_t)b * DIMV + tid * 4) = qk;

        float s = e.x * e.x + e.y * e.y + e.z * e.z + e.w * e.w;
        #pragma unroll
        for (int o = 16; o > 0; o >>= 1) s += __shfl_down_sync(0xffffffffu, s, o);
        __shared__ float red[4];
        if ((tid & 31) == 0) red[tid >> 5] = s;
        __syncthreads();
        if (tid == 0) g_esq[b] = red[0] + red[1] + red[2] + red[3];
    }
}

// ---------------- kernel 2: bf16 HMMA GEMM + top-2-per-segment epilogue ----
// CTA 128x128, BK=64, 256 threads, warp grid 2x4, warp tile 64x32,
// 2 CTAs/SM, 2-stage cp.async; ks-level fragment double-buffering.
__global__ __launch_bounds__(256, 2)
void vq_gemm() {
    extern __shared__ char smem[];                // A0,B0,A1,B1: 4 x 16KB
    __shared__ float s_esq[BN];

    const int tid = threadIdx.x, lane = tid & 31, wid = tid >> 5;
    const int wm = wid >> 2, wn = wid & 3;
    const int rowBase = blockIdx.y * BM;
    const int colBase = blockIdx.x * BN;
    const unsigned sb = smem_u32(smem);

    if (tid < BN) s_esq[tid] = g_esq[colBase + tid];

    float acc[4][4][4];
    #pragma unroll
    for (int mt = 0; mt < 4; mt++)
        #pragma unroll
        for (int nt = 0; nt < 4; nt++)
            #pragma unroll
            for (int q = 0; q < 4; q++) acc[mt][nt][q] = 0.f;

    #define ISSUE_CHUNK(c) do {                                              \
        const int _buf = (c) & 1;                                            \
        const unsigned _aB = sb + _buf * 32768u;                             \
        const unsigned _bB = _aB + 16384u;                                   \
        const __nv_bfloat16* _xp = g_xb + (size_t)rowBase * DIMV + (c) * BK; \
        const __nv_bfloat16* _ep = g_eb + (size_t)colBase * DIMV + (c) * BK; \
        _Pragma("unroll")                                                    \
        for (int _it = 0; _it < 4; _it++) {                                  \
            int _u = tid + _it * 256;                                        \
            int _r = _u >> 3, _c = _u & 7;                                   \
            unsigned _off = _r * 128 + (((_c ^ (_r & 7))) << 4);             \
            asm volatile("cp.async.cg.shared.global [%0], [%1], 16;"         \
                :: "r"(_aB + _off), "l"(_xp + (size_t)_r * DIMV + _c * 8));  \
            asm volatile("cp.async.cg.shared.global [%0], [%1], 16;"         \
                :: "r"(_bB + _off), "l"(_ep + (size_t)_r * DIMV + _c * 8));  \
        }                                                                    \
        asm volatile("cp.async.commit_group;");                              \
    } while (0)

    #define LOAD_FRAGS(ks, s) do {                                           \
        _Pragma("unroll")                                                    \
        for (int _mt = 0; _mt < 4; _mt++) {                                  \
            int rA = wm * 64 + _mt * 16 + (lane & 15);                       \
            int cA = (ks) * 2 + (lane >> 4);                                 \
            unsigned addr = aBase + rA * 128 + (((cA ^ (rA & 7))) << 4);     \
            asm volatile("ldmatrix.sync.aligned.m8n8.x4.shared.b16 "         \
                         "{%0,%1,%2,%3}, [%4];"                              \
                         : "=r"(af[s][_mt][0]), "=r"(af[s][_mt][1]),         \
                           "=r"(af[s][_mt][2]), "=r"(af[s][_mt][3])          \
                         : "r"(addr));                                       \
        }                                                                    \
        _Pragma("unroll")                                                    \
        for (int _nt = 0; _nt < 4; _nt++) {                                  \
            int rB = wn * 32 + _nt * 8 + (lane & 7);                         \
            int cB = (ks) * 2 + ((lane >> 3) & 1);                           \
            unsigned addr = bBase + rB * 128 + (((cB ^ (rB & 7))) << 4);     \
            asm volatile("ldmatrix.sync.aligned.m8n8.x2.shared.b16 "         \
                         "{%0,%1}, [%2];"                                    \
                         : "=r"(bf[s][_nt][0]), "=r"(bf[s][_nt][1])          \
                         : "r"(addr));                                       \
        }                                                                    \
    } while (0)

    ISSUE_CHUNK(0);

    #pragma unroll 1
    for (int c = 0; c < NCHUNK; c++) {
        if (c < NCHUNK - 1) {
            ISSUE_CHUNK(c + 1);
            asm volatile("cp.async.wait_group 1;");
        } else {
            asm volatile("cp.async.wait_group 0;");
        }
        __syncthreads();

        const unsigned aBase = sb + (c & 1) * 32768u;
        const unsigned bBase = aBase + 16384u;

        unsigned af[2][4][4], bf[2][4][2];
        LOAD_FRAGS(0, 0);

        #pragma unroll
        for (int ks = 0; ks < 4; ks++) {
            const int cur = ks & 1, nxt = cur ^ 1;
            if (ks < 3) LOAD_FRAGS(ks + 1, nxt);
            #pragma unroll
            for (int mt = 0; mt < 4; mt++)
                #pragma unroll
                for (int nt = 0; nt < 4; nt++)
                    asm volatile(
                        "mma.sync.aligned.m16n8k16.row.col.f32.bf16.bf16.f32 "
                        "{%0,%1,%2,%3}, {%4,%5,%6,%7}, {%8,%9}, {%0,%1,%2,%3};"
                        : "+f"(acc[mt][nt][0]), "+f"(acc[mt][nt][1]),
                          "+f"(acc[mt][nt][2]), "+f"(acc[mt][nt][3])
                        : "r"(af[cur][mt][0]), "r"(af[cur][mt][1]),
                          "r"(af[cur][mt][2]), "r"(af[cur][mt][3]),
                          "r"(bf[cur][nt][0]), "r"(bf[cur][nt][1]));
        }
        __syncthreads();
    }

    // ---- epilogue: per-(row, 32-col segment) top-2 -------------------------
    const int gq = lane >> 2;
    const int qt = lane & 3;
    float esqv[4][2];
    #pragma unroll
    for (int nt = 0; nt < 4; nt++) {
        int cl = wn * 32 + nt * 8 + qt * 2;
        esqv[nt][0] = s_esq[cl];
        esqv[nt][1] = s_esq[cl + 1];
    }
    const int seg = (colBase + wn * 32) >> 5;

    #pragma unroll
    for (int mt = 0; mt < 4; mt++) {
        int r0 = rowBase + wm * 64 + mt * 16 + gq;
        int r1 = r0 + 8;
        unsigned long long a0 = 0, b0 = 0, a1 = 0, b1 = 0;
        #pragma unroll
        for (int nt = 0; nt < 4; nt++) {
            int cg = colBase + wn * 32 + nt * 8 + qt * 2;
            merge2(a0, b0, pack_score(2.f * acc[mt][nt][0] - esqv[nt][0], cg));
            merge2(a0, b0, pack_score(2.f * acc[mt][nt][1] - esqv[nt][1], cg + 1));
            merge2(a1, b1, pack_score(2.f * acc[mt][nt][2] - esqv[nt][0], cg));
            merge2(a1, b1, pack_score(2.f * acc[mt][nt][3] - esqv[nt][1], cg + 1));
        }
        #pragma unroll
        for (int off = 1; off <= 2; off <<= 1) {
            unsigned long long xa0 = __shfl_xor_sync(0xffffffffu, a0, off);
            unsigned long long xb0 = __shfl_xor_sync(0xffffffffu, b0, off);
            unsigned long long xa1 = __shfl_xor_sync(0xffffffffu, a1, off);
            unsigned long long xb1 = __shfl_xor_sync(0xffffffffu, b1, off);
            merge2(a0, b0, xa0); merge2(a0, b0, xb0);
            merge2(a1, b1, xa1); merge2(a1, b1, xb1);
        }
        if (qt == 0) {
            g_cand[(size_t)r0 * CPR + seg * 2]     = a0;
            g_cand[(size_t)r0 * CPR + seg * 2 + 1] = b0;
            g_cand[(size_t)r1 * CPR + seg * 2]     = a1;
            g_cand[(size_t)r1 * CPR + seg * 2 + 1] = b1;
        }
    }
}

// ---------------- kernel 3: warp-per-row exact fp32 rescore + gather -------
// 256 threads = 8 warps/block, 1 row per warp, no block barriers.
__global__ __launch_bounds__(256)
void vq_rescore(const float* __restrict__ x, const float* __restrict__ embed,
                float* __restrict__ out, int write_idx) {
    const int warp = threadIdx.x >> 5, lane = threadIdx.x & 31;
    const int row = blockIdx.x * 8 + warp;
    __shared__ int s_idx[8][MAXCAND];
    __shared__ int s_cnt[8];
    if (lane == 0) s_cnt[warp] = 0;
    __syncwarp();

    // coalesced candidate scan: 16 u64 per lane
    const unsigned long long* cd = g_cand + (size_t)row * CPR;
    unsigned long long q[16];
    unsigned long long m = 0;
    #pragma unroll
    for (int i = 0; i < 16; i++) {
        q[i] = cd[i * 32 + lane];
        m = max(m, q[i]);
    }
    #pragma unroll
    for (int o = 16; o > 0; o >>= 1)
        m = max(m, __shfl_xor_sync(0xffffffffu, m, o));
    const float thr = unpack_score(m) - EPSF;

    #pragma unroll
    for (int i = 0; i < 16; i++) {
        if (unpack_score(q[i]) >= thr) {
            int k = atomicAdd(&s_cnt[warp], 1);
            if (k < MAXCAND) s_idx[warp][k] = unpack_idx(q[i]);
        }
    }
    __syncwarp();
    const int cnt = min(s_cnt[warp], MAXCAND);

    // cache x row: 16 floats per lane, coalesced float4 loads
    float4 xv[4];
    #pragma unroll
    for (int j = 0; j < 4; j++)
        xv[j] = ((const float4*)(x + (size_t)row * DIMV))[j * 32 + lane];

    unsigned long long best = 0ULL;
    for (int c = 0; c < cnt; c++) {
        const int idx = s_idx[warp][c];
        const float4* ev = (const float4*)(embed + (size_t)idx * DIMV);
        float d = 0.f;
        #pragma unroll
        for (int j = 0; j < 4; j++) {
            float4 e = ev[j * 32 + lane];
            d += xv[j].x * e.x + xv[j].y * e.y + xv[j].z * e.z + xv[j].w * e.w;
        }
        #pragma unroll
        for (int o = 16; o > 0; o >>= 1)
            d += __shfl_xor_sync(0xffffffffu, d, o);
        unsigned long long p = pack_score(2.0f * d - g_esq[idx], idx);
        if (p > best) best = p;            // all lanes hold identical d
    }

    const int widx = unpack_idx(best);
    const float4* ev = (const float4*)(embed + (size_t)widx * DIMV);
    float4* dst = (float4*)(out + (size_t)row * DIMV);
    #pragma unroll
    for (int j = 0; j < 4; j++)
        dst[j * 32 + lane] = ev[j * 32 + lane];
    if (write_idx && lane == 0)
        out[(size_t)NROWS * DIMV + row] = (float)widx;
}

// ---------------- launch ----------------------------------------------------
extern "C" void kernel_launch(void* const* d_in, const int* in_sizes, int n_in,
                              void* d_out, int out_size) {
    const float* x     = (const float*)d_in[0];
    const float* embed = (const float*)d_in[1];
    float* out = (float*)d_out;

    cudaFuncSetAttribute(vq_gemm, cudaFuncAttributeMaxDynamicSharedMemorySize, 65536);

    vq_prep<<<NROWS, 128>>>(x, embed);

    dim3 grid(KCODES / BN, NROWS / BM);   // 64 x 128
    vq_gemm<<<grid, 256, 65536>>>();

    int write_idx = (out_size >= NROWS * DIMV + NROWS) ? 1 : 0;
    vq_rescore<<<NROWS / 8, 256>>>(x, embed, out, write_idx);
}